// round 17
// baseline (speedup 1.0000x reference)
#include <cuda_runtime.h>
#include <math.h>

#define N_NODES  50000
#define N_EDGES  400000
#define NCH      16
#define MAX_DEG  64
#define TOTAL_NK (N_NODES * NCH)            // 800000
#define TOTAL_EK (N_EDGES * NCH)            // 6400000
#define OUT1_OFF (N_NODES * NCH)            // 800000
#define OUT2_OFF (N_NODES * NCH * 4)        // 3200000
#define WPB      8                          // warps per block
#define NCOMP    13                         // s, v(3), M(9)
#define PI10     0.3141592653589793f        // pi/Rcut
#define CRBF     0.44721359549995794f       // sqrt(2/Rcut)

#define GEOM_T       100000                 // threads; each does 4 edges
#define GEOM_BLOCKS  391                    // ceil(100000/256)
#define PACK_BLOCKS  3125                   // 800000/256

// ---- scratch (__device__ globals: no allocation allowed) ----
__device__ int    g_cnt[N_NODES];                 // degree by src (zero at entry, reset by gather)
__device__ float4 g_rec4[N_NODES * MAX_DEG];      // (ux,uy,uz, dst-as-bits) bucketed by src
__device__ int    g_rece[N_NODES * MAX_DEG];      // original edge id per slot
__device__ float  g_rho[TOTAL_EK];                // rho[flat = e*16+k]
__device__ float  g_hp[N_NODES * NCOMP * NCH];    // h transposed: [n][component][k]

// fused prep: geom blocks (4 edges/thread; rho fan-out via sine recurrence)
//           + pack blocks (h transpose)
__global__ void prep_kernel(const float* __restrict__ pos,
                            const int* __restrict__ ei,
                            const float* __restrict__ h0,
                            const float* __restrict__ h1,
                            const float* __restrict__ h2) {
    if (blockIdx.x < GEOM_BLOCKS) {
        int t = blockIdx.x * blockDim.x + threadIdx.x;
        if (t >= GEOM_T) return;
        #pragma unroll
        for (int i = 0; i < 4; ++i) {
            int e = t + i * GEOM_T;                        // 4*100000 == N_EDGES
            int s = ei[e];
            int d = ei[N_EDGES + e];
            float rx = pos[3 * s + 0] - pos[3 * d + 0];
            float ry = pos[3 * s + 1] - pos[3 * d + 1];
            float rz = pos[3 * s + 2] - pos[3 * d + 2];
            float d2 = rx * rx + ry * ry + rz * rz;
            float inv = rsqrtf(d2);                        // 1/r
            int rank = atomicAdd(&g_cnt[s], 1);
            int slot = s * MAX_DEG + rank;
            g_rec4[slot] = make_float4(rx * inv, ry * inv, rz * inv, __int_as_float(d));
            g_rece[slot] = e;

            // rho fan-out: flat indices with e_idx==e are exactly e + 400000*m,
            // m=0..15, with n=m+1 and k=e%16 (400000 = 16*25000).
            // rho(flat) = CRBF * sin((m+1)*PI10*r) / r via Chebyshev recurrence.
            float r = d2 * inv;
            float sn, cs;
            __sincosf(PI10 * r, &sn, &cs);
            float c2 = 2.0f * cs;
            float w  = CRBF * inv;
            g_rho[e] = sn * w;                             // m = 0
            float prev = 0.0f, cur = sn;
            #pragma unroll
            for (int m = 1; m < 16; ++m) {
                float nxt = c2 * cur - prev;               // sin((m+1)theta)
                prev = cur; cur = nxt;
                g_rho[e + m * N_EDGES] = cur * w;          // coalesced across warp
            }
        }
    } else {
        int idx = (blockIdx.x - GEOM_BLOCKS) * blockDim.x + threadIdx.x;
        if (idx >= TOTAL_NK) return;
        int n = idx >> 4;
        int k = idx & 15;
        float* o = g_hp + (n * NCOMP) * NCH + k;
        o[0] = h0[idx];
        const float* vp = h1 + (size_t)idx * 3;
        o[1 * NCH] = vp[0];
        o[2 * NCH] = vp[1];
        o[3 * NCH] = vp[2];
        const float* Mp = h2 + (size_t)idx * 9;
        #pragma unroll
        for (int c = 0; c < 9; ++c) o[(4 + c) * NCH] = Mp[c];
    }
}

// gather: ONE WARP PER NODE (R12 structure). Half-warp h handles edges 2j+h;
// lanes k=0..15 are channels. Packed h rows + precomputed rho -> lean loop.
__global__ void __launch_bounds__(256, 5)
gather_kernel(float* __restrict__ out) {
    __shared__ float4 sh[WPB * 52];        // epilogue staging only

    int warpid = threadIdx.x >> 5;
    int lane   = threadIdx.x & 31;
    int half   = lane >> 4;
    int k      = lane & 15;
    int n      = blockIdx.x * WPB + warpid;   // grid covers exactly N_NODES

    int cnt = g_cnt[n];
    int off = n * MAX_DEG;

    float a0 = 0.0f;
    float a1x = 0.0f, a1y = 0.0f, a1z = 0.0f;
    float a2[9] = {0,0,0,0,0,0,0,0,0};

    int jmax = (cnt + 1) >> 1;
    for (int j = 0; j < jmax; ++j) {
        int idx2 = 2 * j + half;
        bool valid = idx2 < cnt;
        int slot = off + (valid ? idx2 : 0);

        float4 rec = __ldg(&g_rec4[slot]);     // broadcast within half-warp
        int    e   = __ldg(&g_rece[slot]);
        int dst = __float_as_int(rec.w);
        float ux = rec.x, uy = rec.y, uz = rec.z;

        // precomputed radial: one coalesced 64B load per half-warp
        float rho = valid ? __ldg(g_rho + e * NCH + k) : 0.0f;

        // packed h row: 13 LDGs, all independent, issued back-to-back
        const float* hp = g_hp + (size_t)(dst * NCOMP) * NCH + k;
        float s   = __ldg(hp);
        float vx  = __ldg(hp + 1 * NCH),  vy  = __ldg(hp + 2 * NCH),  vz  = __ldg(hp + 3 * NCH);
        float M00 = __ldg(hp + 4 * NCH),  M01 = __ldg(hp + 5 * NCH),  M02 = __ldg(hp + 6 * NCH);
        float M10 = __ldg(hp + 7 * NCH),  M11 = __ldg(hp + 8 * NCH),  M12 = __ldg(hp + 9 * NCH);
        float M20 = __ldg(hp + 10 * NCH), M21 = __ldg(hp + 11 * NCH), M22 = __ldg(hp + 12 * NCH);

        float vd = vx * ux + vy * uy + vz * uz;
        float tr = M00 + M11 + M22;
        float Mux  = M00 * ux + M01 * uy + M02 * uz;
        float Muy  = M10 * ux + M11 * uy + M12 * uz;
        float Muz  = M20 * ux + M21 * uy + M22 * uz;
        float Mtux = M00 * ux + M10 * uy + M20 * uz;
        float Mtuy = M01 * ux + M11 * uy + M21 * uz;
        float Mtuz = M02 * ux + M12 * uy + M22 * uz;
        float uMu  = ux * Mux + uy * Muy + uz * Muz;

        a0 += rho * (2.0f * s + vd + 2.0f * tr + 2.0f * uMu);

        float c1 = rho * (s + 2.0f * vd + tr);
        a1x += c1 * ux + rho * (2.0f * vx + Mux + Mtux);
        a1y += c1 * uy + rho * (2.0f * vy + Muy + Mtuy);
        a1z += c1 * uz + rho * (2.0f * vz + Muz + Mtuz);

        float ct = rho * (s + tr);
        float ax = ct * ux + rho * (vx + 2.0f * (Mux + Mtux));
        float ay = ct * uy + rho * (vy + 2.0f * (Muy + Mtuy));
        float az = ct * uz + rho * (vz + 2.0f * (Muz + Mtuz));
        float r2m = 2.0f * rho;
        a2[0] += r2m * M00 + ax * ux;
        a2[1] += r2m * M01 + ax * uy;
        a2[2] += r2m * M02 + ax * uz;
        a2[3] += r2m * M10 + ay * ux;
        a2[4] += r2m * M11 + ay * uy;
        a2[5] += r2m * M12 + ay * uz;
        a2[6] += r2m * M20 + az * ux;
        a2[7] += r2m * M21 + az * uy;
        a2[8] += r2m * M22 + az * uz;
    }

    // merge the two half-warps (same channels, disjoint edges)
    const unsigned FULL = 0xffffffffu;
    a0  += __shfl_xor_sync(FULL, a0, 16);
    a1x += __shfl_xor_sync(FULL, a1x, 16);
    a1y += __shfl_xor_sync(FULL, a1y, 16);
    a1z += __shfl_xor_sync(FULL, a1z, 16);
    #pragma unroll
    for (int c = 0; c < 9; ++c) a2[c] += __shfl_xor_sync(FULL, a2[c], 16);

    // staged output: per-channel layout in smem, then coalesced f4 stores
    float* w = (float*)(sh + warpid * 52);
    if (half == 0) {
        w[k] = a0;
        w[16 + 3 * k] = a1x; w[17 + 3 * k] = a1y; w[18 + 3 * k] = a1z;
        float* mw = w + 64 + 9 * k;
        #pragma unroll
        for (int c = 0; c < 9; ++c) mw[c] = a2[c];
    }
    __syncwarp();

    const float4* rd = sh + warpid * 52;      // 52 f4 = {out0row, out1row, out2row}
    float4* O0 = (float4*)(out + (size_t)n * 16);
    float4* O1 = (float4*)(out + OUT1_OFF + (size_t)n * 48);
    float4* O2 = (float4*)(out + OUT2_OFF + (size_t)n * 144);
    {
        float4 val = rd[lane];
        float4* p = (lane < 4) ? (O0 + lane)
                  : ((lane < 16) ? (O1 + lane - 4) : (O2 + lane - 16));
        *p = val;
    }
    {
        int t = lane + 32;                     // 32..51
        if (t < 52) O2[t - 16] = rd[t];
    }

    if (lane == 0) g_cnt[n] = 0;               // reset for next launch
}

extern "C" void kernel_launch(void* const* d_in, const int* in_sizes, int n_in,
                              void* d_out, int out_size) {
    const float* h0  = (const float*)d_in[0];
    const float* h1  = (const float*)d_in[1];
    const float* h2  = (const float*)d_in[2];
    const float* pos = (const float*)d_in[3];
    // d_in[4] = channel_weights (provably unused by reference output)
    const int*   ei  = (const int*)d_in[5];
    float* out = (float*)d_out;

    prep_kernel<<<GEOM_BLOCKS + PACK_BLOCKS, 256>>>(pos, ei, h0, h1, h2);
    gather_kernel<<<N_NODES / WPB, 32 * WPB>>>(out);
}